// round 5
// baseline (speedup 1.0000x reference)
#include <cuda_runtime.h>

#define HH   256
#define P5   1024
#define NQ   128
#define GRID_MAIN  152   // GB300 SM count
#define BLOCK_MAIN 768   // 24 warps/SM -> 6 per SMSP, hides MUFU/FMA latency

__device__ float g_w2r[HH];
__device__ float g_c;

__device__ __forceinline__ float tanh_approx(float x) {
    float y; asm("tanh.approx.f32 %0, %1;" : "=f"(y) : "f"(x)); return y;
}
__device__ __forceinline__ float warp_sum(float v) {
    #pragma unroll
    for (int o = 16; o; o >>= 1) v += __shfl_xor_sync(0xffffffffu, v, o);
    return v;
}

// ---------------------------------------------------------------------------
// Kernel 1 (fused setup + w2r): 128 blocks x 256 threads.
// Every block redundantly computes s_i / rhs (16k FMA, overlapped with its
// Wx2 float4 loads already in flight), then its 2 rows of w2r = Wx2 @ rhs.
// Block 0 additionally computes c = bx2 . rhs.
// ---------------------------------------------------------------------------
__global__ __launch_bounds__(256)
void w2r_fused_kernel(
    const float* __restrict__ eq,
    const float* __restrict__ q0, const float* __restrict__ q1,
    const float* __restrict__ q2, const float* __restrict__ q3,
    const float* __restrict__ q4,
    const float* __restrict__ Wq0, const float* __restrict__ bq0,
    const float* __restrict__ Wq1, const float* __restrict__ bq1,
    const float* __restrict__ Wq2, const float* __restrict__ bq2,
    const float* __restrict__ Wq3, const float* __restrict__ bq3,
    const float* __restrict__ Wq4, const float* __restrict__ bq4,
    const float* __restrict__ bx2,
    const float* __restrict__ Wx2)
{
    __shared__ float s[5][64];          // [i][p*16+x]
    __shared__ float t01[16][16];       // [x][b*4+d]
    __shared__ float t23[16][16];       // [x][f*4+m]
    __shared__ float partA[5][4], partB[5][4];
    __shared__ float sA[5], sB[5];
    __shared__ float red[8];

    const int tid  = threadIdx.x;
    const int lane = tid & 31;
    const int wrp  = tid >> 5;
    const int h0   = blockIdx.x * 2;

    // Issue the big independent loads FIRST so they overlap the setup chain.
    const float4 wrow0 = reinterpret_cast<const float4*>(Wx2 + h0 * P5)[tid];
    const float4 wrow1 = reinterpret_cast<const float4*>(Wx2 + (h0 + 1) * P5)[tid];

    const float eqv = eq[0];

    // A_i = sum_r y_r q_r, B_i = sum_r y_r,  y = exp(-q^2*eq). 128 active thr.
    if (tid < NQ) {
        const float* qp[5] = {q0, q1, q2, q3, q4};
        #pragma unroll
        for (int i = 0; i < 5; i++) {
            float q = qp[i][tid];
            float y = __expf(-q * q * eqv);
            float a = warp_sum(y * q);
            float b = warp_sum(y);
            if (lane == 0) { partA[i][wrp] = a; partB[i][wrp] = b; }
        }
    }
    __syncthreads();
    if (tid < 5) {
        sA[tid] = partA[tid][0] + partA[tid][1] + partA[tid][2] + partA[tid][3];
        sB[tid] = partB[tid][0] + partB[tid][1] + partB[tid][2] + partB[tid][3];
    }
    __syncthreads();

    if (tid < 64) {
        s[0][tid] = sA[0] * Wq0[tid] + sB[0] * bq0[tid];
        s[1][tid] = sA[1] * Wq1[tid] + sB[1] * bq1[tid];
        s[2][tid] = sA[2] * Wq2[tid] + sB[2] * bq2[tid];
        s[3][tid] = sA[3] * Wq3[tid] + sB[3] * bq3[tid];
        s[4][tid] = sA[4] * Wq4[tid] + sB[4] * bq4[tid];
    }
    __syncthreads();

    {
        int pq = tid >> 4;       // (p0*4+p1)
        int x  = tid & 15;
        t01[x][pq] = s[0][(pq >> 2) * 16 + x] * s[1][(pq & 3) * 16 + x];
        t23[x][pq] = s[2][(pq >> 2) * 16 + x] * s[3][(pq & 3) * 16 + x];
    }
    __syncthreads();

    // rhs quad owned by this thread: idx = 4*tid + v, v in 0..3
    const int bd = tid >> 4;
    const int fm = tid & 15;
    float a0 = 0.f, a1 = 0.f, a2 = 0.f, a3 = 0.f;
    #pragma unroll
    for (int x = 0; x < 16; x++) {
        float u = t01[x][bd] * t23[x][fm];
        a0 = fmaf(u, s[4][x],      a0);
        a1 = fmaf(u, s[4][16 + x], a1);
        a2 = fmaf(u, s[4][32 + x], a2);
        a3 = fmaf(u, s[4][48 + x], a3);
    }

    // w2r rows for this block (rhs quad aligns exactly with the float4 loads)
    float d0 = wrow0.x * a0 + wrow0.y * a1 + wrow0.z * a2 + wrow0.w * a3;
    float d1 = wrow1.x * a0 + wrow1.y * a1 + wrow1.z * a2 + wrow1.w * a3;
    d0 = warp_sum(d0);
    d1 = warp_sum(d1);
    if (lane == 0) red[wrp] = d0;
    __syncthreads();
    if (tid == 0) {
        float t = 0.f;
        #pragma unroll
        for (int w = 0; w < 8; w++) t += red[w];
        g_w2r[h0] = t;
    }
    __syncthreads();
    if (lane == 0) red[wrp] = d1;
    __syncthreads();
    if (tid == 0) {
        float t = 0.f;
        #pragma unroll
        for (int w = 0; w < 8; w++) t += red[w];
        g_w2r[h0 + 1] = t;
    }

    // Block 0: c = bx2 . rhs
    if (blockIdx.x == 0) {
        float4 bv = reinterpret_cast<const float4*>(bx2)[tid];
        float cp = a0 * bv.x + a1 * bv.y + a2 * bv.z + a3 * bv.w;
        cp = warp_sum(cp);
        __syncthreads();
        if (lane == 0) red[wrp] = cp;
        __syncthreads();
        if (tid == 0) {
            float c = 0.f;
            #pragma unroll
            for (int w = 0; w < 8; w++) c += red[w];
            g_c = c;
        }
    }
}

// ---------------------------------------------------------------------------
// Kernel 2: out[n] = c + sum_h tanh(x_n . Wx1[:,h] + bx1[h]) * w2r[h]
// tanh via MUFU.TANH: 1 MUFU + 4 FMA per (n,h).
// 768 threads/block (24 warps/SM), 1 point/thread, grid = 152 = #SMs.
// ---------------------------------------------------------------------------
__global__ __launch_bounds__(BLOCK_MAIN)
void main_kernel(const float* __restrict__ input,
                 const float* __restrict__ Wx1,
                 const float* __restrict__ bx1,
                 float* __restrict__ out, int N)
{
    __shared__ float4 sW[HH];
    __shared__ float  sR[HH];
    __shared__ float  sC;
    const int tid = threadIdx.x;
    if (tid < HH) {
        sW[tid] = make_float4(Wx1[tid], Wx1[HH + tid], Wx1[2 * HH + tid], bx1[tid]);
        sR[tid] = g_w2r[tid];
        if (tid == 0) sC = g_c;
    }
    __syncthreads();

    const int ppb  = (N + GRID_MAIN - 1) / GRID_MAIN;   // 658 for N=100000
    const int base = blockIdx.x * ppb;
    const int end  = min(base + ppb, N);
    const float c  = sC;

    // ppb <= BLOCK_MAIN at N=100000 -> exactly one chunk iteration.
    for (int n0 = base; n0 < end; n0 += BLOCK_MAIN) {
        const int  n = n0 + tid;
        const bool v = n < end;
        float x0 = 0.f, x1 = 0.f, x2 = 0.f;
        if (v) { x0 = input[3 * n]; x1 = input[3 * n + 1]; x2 = input[3 * n + 2]; }

        float acc = c;
        #pragma unroll 8
        for (int h = 0; h < HH; h++) {
            float4 w = sW[h];
            float z = fmaf(x2, w.z, fmaf(x1, w.y, fmaf(x0, w.x, w.w)));
            acc = fmaf(tanh_approx(z), sR[h], acc);
        }
        if (v) out[n] = acc;
    }
}

// ---------------------------------------------------------------------------
extern "C" void kernel_launch(void* const* d_in, const int* in_sizes, int n_in,
                              void* d_out, int out_size)
{
    const float* input = (const float*)d_in[0];
    const float* eq    = (const float*)d_in[1];
    const float* q0    = (const float*)d_in[2];
    const float* q1    = (const float*)d_in[3];
    const float* q2    = (const float*)d_in[4];
    const float* q3    = (const float*)d_in[5];
    const float* q4    = (const float*)d_in[6];
    const float* Wx1   = (const float*)d_in[7];
    const float* bx1   = (const float*)d_in[8];
    const float* Wx2   = (const float*)d_in[9];
    const float* bx2   = (const float*)d_in[10];
    const float* Wq0   = (const float*)d_in[11];
    const float* bq0   = (const float*)d_in[12];
    const float* Wq1   = (const float*)d_in[13];
    const float* bq1   = (const float*)d_in[14];
    const float* Wq2   = (const float*)d_in[15];
    const float* bq2   = (const float*)d_in[16];
    const float* Wq3   = (const float*)d_in[17];
    const float* bq3   = (const float*)d_in[18];
    const float* Wq4   = (const float*)d_in[19];
    const float* bq4   = (const float*)d_in[20];

    const int N = in_sizes[0] / 3;

    w2r_fused_kernel<<<HH / 2, 256>>>(eq, q0, q1, q2, q3, q4,
                                      Wq0, bq0, Wq1, bq1, Wq2, bq2,
                                      Wq3, bq3, Wq4, bq4, bx2, Wx2);
    main_kernel<<<GRID_MAIN, BLOCK_MAIN>>>(input, Wx1, bx1, (float*)d_out, N);
}

// round 6
// speedup vs baseline: 1.0935x; 1.0935x over previous
#include <cuda_runtime.h>

#define HH   256
#define P5   1024
#define NQ   128
#define GRID_MAIN  152   // GB300 SM count
#define BLOCK_MAIN 384   // 12 warps/SM, 3/SMSP; 2 points/thread amortizes LDS

__device__ float g_w2r[HH];
__device__ float g_c;

__device__ __forceinline__ float tanh_approx(float x) {
    float y; asm("tanh.approx.f32 %0, %1;" : "=f"(y) : "f"(x)); return y;
}
__device__ __forceinline__ float warp_sum(float v) {
    #pragma unroll
    for (int o = 16; o; o >>= 1) v += __shfl_xor_sync(0xffffffffu, v, o);
    return v;
}

// ---------------------------------------------------------------------------
// Kernel 1 (fused setup + w2r): 128 blocks x 256 threads.
// Every block redundantly computes s_i / rhs (16k FMA, overlapped with its
// Wx2 float4 loads already in flight), then its 2 rows of w2r = Wx2 @ rhs.
// Block 0 additionally computes c = bx2 . rhs.
// ---------------------------------------------------------------------------
__global__ __launch_bounds__(256)
void w2r_fused_kernel(
    const float* __restrict__ eq,
    const float* __restrict__ q0, const float* __restrict__ q1,
    const float* __restrict__ q2, const float* __restrict__ q3,
    const float* __restrict__ q4,
    const float* __restrict__ Wq0, const float* __restrict__ bq0,
    const float* __restrict__ Wq1, const float* __restrict__ bq1,
    const float* __restrict__ Wq2, const float* __restrict__ bq2,
    const float* __restrict__ Wq3, const float* __restrict__ bq3,
    const float* __restrict__ Wq4, const float* __restrict__ bq4,
    const float* __restrict__ bx2,
    const float* __restrict__ Wx2)
{
    __shared__ float s[5][64];          // [i][p*16+x]
    __shared__ float t01[16][16];       // [x][b*4+d]
    __shared__ float t23[16][16];       // [x][f*4+m]
    __shared__ float partA[5][4], partB[5][4];
    __shared__ float sA[5], sB[5];
    __shared__ float red[8];

    const int tid  = threadIdx.x;
    const int lane = tid & 31;
    const int wrp  = tid >> 5;
    const int h0   = blockIdx.x * 2;

    // Issue the big independent loads FIRST so they overlap the setup chain.
    const float4 wrow0 = reinterpret_cast<const float4*>(Wx2 + h0 * P5)[tid];
    const float4 wrow1 = reinterpret_cast<const float4*>(Wx2 + (h0 + 1) * P5)[tid];

    const float eqv = eq[0];

    // A_i = sum_r y_r q_r, B_i = sum_r y_r,  y = exp(-q^2*eq). 128 active thr.
    if (tid < NQ) {
        const float* qp[5] = {q0, q1, q2, q3, q4};
        #pragma unroll
        for (int i = 0; i < 5; i++) {
            float q = qp[i][tid];
            float y = __expf(-q * q * eqv);
            float a = warp_sum(y * q);
            float b = warp_sum(y);
            if (lane == 0) { partA[i][wrp] = a; partB[i][wrp] = b; }
        }
    }
    __syncthreads();
    if (tid < 5) {
        sA[tid] = partA[tid][0] + partA[tid][1] + partA[tid][2] + partA[tid][3];
        sB[tid] = partB[tid][0] + partB[tid][1] + partB[tid][2] + partB[tid][3];
    }
    __syncthreads();

    if (tid < 64) {
        s[0][tid] = sA[0] * Wq0[tid] + sB[0] * bq0[tid];
        s[1][tid] = sA[1] * Wq1[tid] + sB[1] * bq1[tid];
        s[2][tid] = sA[2] * Wq2[tid] + sB[2] * bq2[tid];
        s[3][tid] = sA[3] * Wq3[tid] + sB[3] * bq3[tid];
        s[4][tid] = sA[4] * Wq4[tid] + sB[4] * bq4[tid];
    }
    __syncthreads();

    {
        int pq = tid >> 4;       // (p0*4+p1)
        int x  = tid & 15;
        t01[x][pq] = s[0][(pq >> 2) * 16 + x] * s[1][(pq & 3) * 16 + x];
        t23[x][pq] = s[2][(pq >> 2) * 16 + x] * s[3][(pq & 3) * 16 + x];
    }
    __syncthreads();

    // rhs quad owned by this thread: idx = 4*tid + v, v in 0..3
    const int bd = tid >> 4;
    const int fm = tid & 15;
    float a0 = 0.f, a1 = 0.f, a2 = 0.f, a3 = 0.f;
    #pragma unroll
    for (int x = 0; x < 16; x++) {
        float u = t01[x][bd] * t23[x][fm];
        a0 = fmaf(u, s[4][x],      a0);
        a1 = fmaf(u, s[4][16 + x], a1);
        a2 = fmaf(u, s[4][32 + x], a2);
        a3 = fmaf(u, s[4][48 + x], a3);
    }

    // w2r rows for this block (rhs quad aligns exactly with the float4 loads)
    float d0 = wrow0.x * a0 + wrow0.y * a1 + wrow0.z * a2 + wrow0.w * a3;
    float d1 = wrow1.x * a0 + wrow1.y * a1 + wrow1.z * a2 + wrow1.w * a3;
    d0 = warp_sum(d0);
    d1 = warp_sum(d1);
    if (lane == 0) red[wrp] = d0;
    __syncthreads();
    if (tid == 0) {
        float t = 0.f;
        #pragma unroll
        for (int w = 0; w < 8; w++) t += red[w];
        g_w2r[h0] = t;
    }
    __syncthreads();
    if (lane == 0) red[wrp] = d1;
    __syncthreads();
    if (tid == 0) {
        float t = 0.f;
        #pragma unroll
        for (int w = 0; w < 8; w++) t += red[w];
        g_w2r[h0 + 1] = t;
    }

    // Block 0: c = bx2 . rhs
    if (blockIdx.x == 0) {
        float4 bv = reinterpret_cast<const float4*>(bx2)[tid];
        float cp = a0 * bv.x + a1 * bv.y + a2 * bv.z + a3 * bv.w;
        cp = warp_sum(cp);
        __syncthreads();
        if (lane == 0) red[wrp] = cp;
        __syncthreads();
        if (tid == 0) {
            float c = 0.f;
            #pragma unroll
            for (int w = 0; w < 8; w++) c += red[w];
            g_c = c;
        }
    }
}

// ---------------------------------------------------------------------------
// Kernel 2: out[n] = c + sum_h tanh(x_n . Wx1[:,h] + bx1[h]) * w2r[h]
// tanh via MUFU.TANH: 1 MUFU + 4 FMA per (n,h).
// 384 threads/block, 2 points/thread: each (sW,sR) LDS pair feeds 2 points,
// halving the smem-crossbar load that bound the previous version.
// ---------------------------------------------------------------------------
__global__ __launch_bounds__(BLOCK_MAIN)
void main_kernel(const float* __restrict__ input,
                 const float* __restrict__ Wx1,
                 const float* __restrict__ bx1,
                 float* __restrict__ out, int N)
{
    __shared__ float4 sW[HH];
    __shared__ float  sR[HH];
    __shared__ float  sC;
    const int tid = threadIdx.x;
    if (tid < HH) {
        sW[tid] = make_float4(Wx1[tid], Wx1[HH + tid], Wx1[2 * HH + tid], bx1[tid]);
        sR[tid] = g_w2r[tid];
        if (tid == 0) sC = g_c;
    }
    __syncthreads();

    const int ppb  = (N + GRID_MAIN - 1) / GRID_MAIN;   // 658 for N=100000
    const int base = blockIdx.x * ppb;
    const int end  = min(base + ppb, N);
    const float c  = sC;

    // ppb <= 2*BLOCK_MAIN at N=100000 -> exactly one chunk iteration.
    for (int c0 = base; c0 < end; c0 += 2 * BLOCK_MAIN) {
        const int  n0 = c0 + tid;
        const int  n1 = n0 + BLOCK_MAIN;
        const bool v0 = n0 < end;
        const bool v1 = n1 < end;

        float x00 = 0.f, x01 = 0.f, x02 = 0.f;
        float x10 = 0.f, x11 = 0.f, x12 = 0.f;
        if (v0) { x00 = input[3*n0]; x01 = input[3*n0+1]; x02 = input[3*n0+2]; }
        if (v1) { x10 = input[3*n1]; x11 = input[3*n1+1]; x12 = input[3*n1+2]; }

        float acc0 = c, acc1 = c;
        #pragma unroll 8
        for (int h = 0; h < HH; h++) {
            float4 w = sW[h];
            float  r = sR[h];
            float z0 = fmaf(x02, w.z, fmaf(x01, w.y, fmaf(x00, w.x, w.w)));
            float z1 = fmaf(x12, w.z, fmaf(x11, w.y, fmaf(x10, w.x, w.w)));
            acc0 = fmaf(tanh_approx(z0), r, acc0);
            acc1 = fmaf(tanh_approx(z1), r, acc1);
        }
        if (v0) out[n0] = acc0;
        if (v1) out[n1] = acc1;
    }
}

// ---------------------------------------------------------------------------
extern "C" void kernel_launch(void* const* d_in, const int* in_sizes, int n_in,
                              void* d_out, int out_size)
{
    const float* input = (const float*)d_in[0];
    const float* eq    = (const float*)d_in[1];
    const float* q0    = (const float*)d_in[2];
    const float* q1    = (const float*)d_in[3];
    const float* q2    = (const float*)d_in[4];
    const float* q3    = (const float*)d_in[5];
    const float* q4    = (const float*)d_in[6];
    const float* Wx1   = (const float*)d_in[7];
    const float* bx1   = (const float*)d_in[8];
    const float* Wx2   = (const float*)d_in[9];
    const float* bx2   = (const float*)d_in[10];
    const float* Wq0   = (const float*)d_in[11];
    const float* bq0   = (const float*)d_in[12];
    const float* Wq1   = (const float*)d_in[13];
    const float* bq1   = (const float*)d_in[14];
    const float* Wq2   = (const float*)d_in[15];
    const float* bq2   = (const float*)d_in[16];
    const float* Wq3   = (const float*)d_in[17];
    const float* bq3   = (const float*)d_in[18];
    const float* Wq4   = (const float*)d_in[19];
    const float* bq4   = (const float*)d_in[20];

    const int N = in_sizes[0] / 3;

    w2r_fused_kernel<<<HH / 2, 256>>>(eq, q0, q1, q2, q3, q4,
                                      Wq0, bq0, Wq1, bq1, Wq2, bq2,
                                      Wq3, bq3, Wq4, bq4, bx2, Wx2);
    main_kernel<<<GRID_MAIN, BLOCK_MAIN>>>(input, Wx1, bx1, (float*)d_out, N);
}